// round 1
// baseline (speedup 1.0000x reference)
#include <cuda_runtime.h>
#include <cuda_bf16.h>

// ---------------------------------------------------------------------------
// QCNNHybrid: BN(batch stats) -> 8 tiny dense layers, B = 1,048,576 rows x 8.
// 3-kernel plan:
//   k_stats : per-block partial sums/sumsq of x columns (deterministic).
//   k_fold  : reduce partials, fold BN into layer-1 weights, pack all params
//             into one contiguous __device__ array.
//   k_main  : per-thread 4 rows, f32x2 packed FMA chain, MUFU tanh.
// ---------------------------------------------------------------------------

#define NBLK_STATS 1024
#define NTHREADS   256

__device__ float g_partials[NBLK_STATS * 16];
// packed params: Wfm'(128) bfm'(16) Wc1(256) bc1(16) Wp1(192) bp1(12)
//                Wc2(96) bc2(8) Wp2(32) bp2(4) Wc3(16) bc3(4)
//                Wr(16) br(4) Wh(4) bh(1)  => 805 floats
#define P_WFM 0
#define P_BFM 128
#define P_WC1 144
#define P_BC1 400
#define P_WP1 416
#define P_BP1 608
#define P_WC2 620
#define P_BC2 716
#define P_WP2 724
#define P_BP2 756
#define P_WC3 760
#define P_BC3 776
#define P_WR  780
#define P_BR  796
#define P_WH  800
#define P_BH  804
#define P_TOTAL 805
__device__ float g_params[P_TOTAL + 3];

// ------------------------------- f32x2 helpers -----------------------------
typedef unsigned long long u64;

__device__ __forceinline__ u64 pk2(float a, float b) {
    u64 r;
    asm("mov.b64 %0,{%1,%2};" : "=l"(r) : "f"(a), "f"(b));
    return r;
}
__device__ __forceinline__ void upk2(u64 v, float& a, float& b) {
    asm("mov.b64 {%0,%1},%2;" : "=f"(a), "=f"(b) : "l"(v));
}
__device__ __forceinline__ u64 ffma2(u64 a, u64 b, u64 c) {
    u64 d;
    asm("fma.rn.f32x2 %0,%1,%2,%3;" : "=l"(d) : "l"(a), "l"(b), "l"(c));
    return d;
}
__device__ __forceinline__ u64 fadd2(u64 a, u64 b) {
    u64 d;
    asm("add.rn.f32x2 %0,%1,%2;" : "=l"(d) : "l"(a), "l"(b));
    return d;
}
__device__ __forceinline__ float tanh_ap(float x) {
    float y;
    asm("tanh.approx.f32 %0,%1;" : "=f"(y) : "f"(x));
    return y;
}
__device__ __forceinline__ u64 tanh2(u64 v) {
    float a, b;
    upk2(v, a, b);
    return pk2(tanh_ap(a), tanh_ap(b));
}
__device__ __forceinline__ u64 relu2(u64 v) {
    float a, b;
    upk2(v, a, b);
    return pk2(fmaxf(a, 0.0f), fmaxf(b, 0.0f));
}

// one dense layer on two f32x2 packs (4 rows), optional tanh
template <int DIN, int DOUT, bool ACT>
__device__ __forceinline__ void layerT(const float* __restrict__ W,
                                       const float* __restrict__ Bv,
                                       const u64* a0, const u64* a1,
                                       u64* o0, u64* o1) {
#pragma unroll
    for (int j = 0; j < DOUT; j++) {
        float bj = Bv[j];
        u64 acc0 = pk2(bj, bj);
        u64 acc1 = acc0;
#pragma unroll
        for (int i = 0; i < DIN; i++) {
            float w = W[i * DOUT + j];
            u64 wp = pk2(w, w);
            acc0 = ffma2(a0[i], wp, acc0);
            acc1 = ffma2(a1[i], wp, acc1);
        }
        if (ACT) { acc0 = tanh2(acc0); acc1 = tanh2(acc1); }
        o0[j] = acc0;
        o1[j] = acc1;
    }
}

// ------------------------------- kernel A: stats ---------------------------
__global__ void __launch_bounds__(NTHREADS) k_stats(const float* __restrict__ x,
                                                    int nrows) {
    int g = blockIdx.x * NTHREADS + threadIdx.x;
    long base = (long)g * 4;
    float s[8], q[8];
#pragma unroll
    for (int c = 0; c < 8; c++) { s[c] = 0.0f; q[c] = 0.0f; }
    if (base + 3 < nrows) {
        const float4* xv = (const float4*)(x + base * 8);
#pragma unroll
        for (int r = 0; r < 4; r++) {
            float4 a = xv[r * 2], b = xv[r * 2 + 1];
            s[0] += a.x; q[0] += a.x * a.x;
            s[1] += a.y; q[1] += a.y * a.y;
            s[2] += a.z; q[2] += a.z * a.z;
            s[3] += a.w; q[3] += a.w * a.w;
            s[4] += b.x; q[4] += b.x * b.x;
            s[5] += b.y; q[5] += b.y * b.y;
            s[6] += b.z; q[6] += b.z * b.z;
            s[7] += b.w; q[7] += b.w * b.w;
        }
    }
#pragma unroll
    for (int c = 0; c < 8; c++) {
#pragma unroll
        for (int o = 16; o > 0; o >>= 1) {
            s[c] += __shfl_xor_sync(0xffffffffu, s[c], o);
            q[c] += __shfl_xor_sync(0xffffffffu, q[c], o);
        }
    }
    __shared__ float sm[8][16];
    int warp = threadIdx.x >> 5, lane = threadIdx.x & 31;
    if (lane == 0) {
#pragma unroll
        for (int c = 0; c < 8; c++) { sm[warp][c] = s[c]; sm[warp][8 + c] = q[c]; }
    }
    __syncthreads();
    if (threadIdx.x < 16) {
        float acc = 0.0f;
#pragma unroll
        for (int w = 0; w < 8; w++) acc += sm[w][threadIdx.x];
        g_partials[blockIdx.x * 16 + threadIdx.x] = acc;
    }
}

// ------------------------------- kernel B: fold ----------------------------
__global__ void __launch_bounds__(NTHREADS) k_fold(
    const float* __restrict__ bn_g, const float* __restrict__ bn_b,
    const float* __restrict__ w_fm, const float* __restrict__ b_fm,
    const float* __restrict__ w_c1, const float* __restrict__ b_c1,
    const float* __restrict__ w_p1, const float* __restrict__ b_p1,
    const float* __restrict__ w_c2, const float* __restrict__ b_c2,
    const float* __restrict__ w_p2, const float* __restrict__ b_p2,
    const float* __restrict__ w_c3, const float* __restrict__ b_c3,
    const float* __restrict__ w_r,  const float* __restrict__ b_r,
    const float* __restrict__ w_h,  const float* __restrict__ b_h,
    float invB, int nblk) {
    int tid = threadIdx.x;
    __shared__ float s1[256];
    __shared__ float totals[16];
    __shared__ float scale[8], shift[8];

    // stage 1: 16 chunks x 16 columns
    {
        int col = tid >> 4, chunk = tid & 15;
        int per = (nblk + 15) / 16;
        int b0 = chunk * per;
        int b1 = b0 + per; if (b1 > nblk) b1 = nblk;
        float acc = 0.0f;
        for (int b = b0; b < b1; b++) acc += g_partials[b * 16 + col];
        s1[col * 16 + chunk] = acc;
    }
    __syncthreads();
    if (tid < 16) {
        float acc = 0.0f;
#pragma unroll
        for (int k = 0; k < 16; k++) acc += s1[tid * 16 + k];
        totals[tid] = acc;
    }
    __syncthreads();
    if (tid < 8) {
        float mu = totals[tid] * invB;
        float var = totals[8 + tid] * invB - mu * mu;
        float sc = bn_g[tid] * rsqrtf(var + 1e-5f);
        scale[tid] = sc;
        shift[tid] = bn_b[tid] - mu * sc;
    }
    __syncthreads();
    // folded first layer
    if (tid < 128) g_params[P_WFM + tid] = scale[tid >> 4] * w_fm[tid];
    if (tid < 16) {
        float acc = b_fm[tid];
#pragma unroll
        for (int i = 0; i < 8; i++) acc += shift[i] * w_fm[i * 16 + tid];
        g_params[P_BFM + tid] = acc;
    }
    // copy everything else
    if (tid < 256) g_params[P_WC1 + tid] = w_c1[tid];
    if (tid < 16)  g_params[P_BC1 + tid] = b_c1[tid];
    if (tid < 192) g_params[P_WP1 + tid] = w_p1[tid];
    if (tid < 12)  g_params[P_BP1 + tid] = b_p1[tid];
    if (tid < 96)  g_params[P_WC2 + tid] = w_c2[tid];
    if (tid < 8)   g_params[P_BC2 + tid] = b_c2[tid];
    if (tid < 32)  g_params[P_WP2 + tid] = w_p2[tid];
    if (tid < 4)   g_params[P_BP2 + tid] = b_p2[tid];
    if (tid < 16)  g_params[P_WC3 + tid] = w_c3[tid];
    if (tid < 4)   g_params[P_BC3 + tid] = b_c3[tid];
    if (tid < 16)  g_params[P_WR + tid]  = w_r[tid];
    if (tid < 4)   g_params[P_BR + tid]  = b_r[tid];
    if (tid < 4)   g_params[P_WH + tid]  = w_h[tid];
    if (tid < 1)   g_params[P_BH + tid]  = b_h[tid];
}

// ------------------------------- kernel C: main ----------------------------
__global__ void __launch_bounds__(NTHREADS) k_main(const float* __restrict__ x,
                                                   float* __restrict__ out,
                                                   int nrows) {
    __shared__ float sp[P_TOTAL];
    for (int i = threadIdx.x; i < P_TOTAL; i += NTHREADS) sp[i] = g_params[i];
    __syncthreads();

    int t = blockIdx.x * NTHREADS + threadIdx.x;
    long base = (long)t * 4;
    if (base + 3 >= nrows + 1) { /* exact division expected */ }
    if (base >= nrows) return;

    const float4* xv = (const float4*)(x + base * 8);
    float4 r0a = xv[0], r0b = xv[1];
    float4 r1a = xv[2], r1b = xv[3];
    float4 r2a = xv[4], r2b = xv[5];
    float4 r3a = xv[6], r3b = xv[7];

    u64 A0[16], A1[16], B0[16], B1[16];
    // pack rows (0,1) -> A0, rows (2,3) -> A1
    A0[0] = pk2(r0a.x, r1a.x); A1[0] = pk2(r2a.x, r3a.x);
    A0[1] = pk2(r0a.y, r1a.y); A1[1] = pk2(r2a.y, r3a.y);
    A0[2] = pk2(r0a.z, r1a.z); A1[2] = pk2(r2a.z, r3a.z);
    A0[3] = pk2(r0a.w, r1a.w); A1[3] = pk2(r2a.w, r3a.w);
    A0[4] = pk2(r0b.x, r1b.x); A1[4] = pk2(r2b.x, r3b.x);
    A0[5] = pk2(r0b.y, r1b.y); A1[5] = pk2(r2b.y, r3b.y);
    A0[6] = pk2(r0b.z, r1b.z); A1[6] = pk2(r2b.z, r3b.z);
    A0[7] = pk2(r0b.w, r1b.w); A1[7] = pk2(r2b.w, r3b.w);

    layerT<8, 16, true>(sp + P_WFM, sp + P_BFM, A0, A1, B0, B1);   // feature_map
    layerT<16, 16, true>(sp + P_WC1, sp + P_BC1, B0, B1, A0, A1);  // conv1
    layerT<16, 12, true>(sp + P_WP1, sp + P_BP1, A0, A1, B0, B1);  // pool1
    layerT<12, 8, true>(sp + P_WC2, sp + P_BC2, B0, B1, A0, A1);   // conv2
    layerT<8, 4, true>(sp + P_WP2, sp + P_BP2, A0, A1, B0, B1);    // pool2
    layerT<4, 4, true>(sp + P_WC3, sp + P_BC3, B0, B1, A0, A1);    // conv3 -> A
    layerT<4, 4, false>(sp + P_WR, sp + P_BR, A0, A1, B0, B1);     // residual pre-relu
#pragma unroll
    for (int j = 0; j < 4; j++) {
        A0[j] = fadd2(A0[j], relu2(B0[j]));
        A1[j] = fadd2(A1[j], relu2(B1[j]));
    }
    // head: [4 -> 1] then sigmoid(x) = 0.5*tanh(0.5x)+0.5
    float bh = sp[P_BH];
    u64 acc0 = pk2(bh, bh), acc1 = acc0;
#pragma unroll
    for (int i = 0; i < 4; i++) {
        float w = sp[P_WH + i];
        u64 wp = pk2(w, w);
        acc0 = ffma2(A0[i], wp, acc0);
        acc1 = ffma2(A1[i], wp, acc1);
    }
    float z0, z1, z2, z3;
    upk2(acc0, z0, z1);
    upk2(acc1, z2, z3);
    float4 o;
    o.x = fmaf(0.5f, tanh_ap(0.5f * z0), 0.5f);
    o.y = fmaf(0.5f, tanh_ap(0.5f * z1), 0.5f);
    o.z = fmaf(0.5f, tanh_ap(0.5f * z2), 0.5f);
    o.w = fmaf(0.5f, tanh_ap(0.5f * z3), 0.5f);
    ((float4*)out)[t] = o;
}

// ------------------------------- launch ------------------------------------
extern "C" void kernel_launch(void* const* d_in, const int* in_sizes, int n_in,
                              void* d_out, int out_size) {
    const float* x    = (const float*)d_in[0];
    const float* bn_g = (const float*)d_in[1];
    const float* bn_b = (const float*)d_in[2];
    const float* w_fm = (const float*)d_in[3];
    const float* b_fm = (const float*)d_in[4];
    const float* w_c1 = (const float*)d_in[5];
    const float* b_c1 = (const float*)d_in[6];
    const float* w_p1 = (const float*)d_in[7];
    const float* b_p1 = (const float*)d_in[8];
    const float* w_c2 = (const float*)d_in[9];
    const float* b_c2 = (const float*)d_in[10];
    const float* w_p2 = (const float*)d_in[11];
    const float* b_p2 = (const float*)d_in[12];
    const float* w_c3 = (const float*)d_in[13];
    const float* b_c3 = (const float*)d_in[14];
    const float* w_r  = (const float*)d_in[15];
    const float* b_r  = (const float*)d_in[16];
    const float* w_h  = (const float*)d_in[17];
    const float* b_h  = (const float*)d_in[18];
    float* out = (float*)d_out;

    int nrows = in_sizes[0] / 8;
    int nthreads_total = nrows / 4;               // 262144 for B=1M
    int nblk = (nthreads_total + NTHREADS - 1) / NTHREADS;  // 1024

    k_stats<<<nblk, NTHREADS>>>(x, nrows);
    k_fold<<<1, NTHREADS>>>(bn_g, bn_b, w_fm, b_fm, w_c1, b_c1, w_p1, b_p1,
                            w_c2, b_c2, w_p2, b_p2, w_c3, b_c3, w_r, b_r,
                            w_h, b_h, 1.0f / (float)nrows, nblk);
    k_main<<<nblk, NTHREADS>>>(x, out, nrows);
}